// round 13
// baseline (speedup 1.0000x reference)
#include <cuda_runtime.h>
#include <cuda_fp16.h>
#include <cstdint>

// Problem constants
#define B_   64
#define T_   2048
#define D_   512
#define H_   64
#define T1   683      // conv1 output length
#define T2   228      // conv2 output length
#define KDIM 1536     // 3*512
#define NCH  128      // 2*H
#define KSEL 32       // top-k

#define NCHUNK 48     // KDIM / 32
#define BKC    32     // K elems per chunk

#define MROWS (B_ * T1)   // 43712 flattened (b,t) rows
#define MTILE 160
#define NTILES ((MROWS + MTILE - 1) / MTILE)   // 274
#define WELEMS (NCH * KDIM)                     // 196608
#define WSLICE ((WELEMS + NTILES - 1) / NTILES) // 718

// Device scratch
__device__ __half g_Wh[NCH * KDIM];   // weights [c][k] fp16
__device__ float g_part[B_];          // per-batch score partial sums (zero-init; last CTA resets)
__device__ int   g_idx[KSEL];
__device__ unsigned g_arrive = 0;     // start grid barrier counter (wraps -> self-reset)
__device__ unsigned g_sense = 0;      // start grid barrier sense (alternates per replay)
__device__ unsigned g_done = 0;       // completion counter (wraps -> self-reset)

// ---------------------------------------------------------------------------
// helpers
// ---------------------------------------------------------------------------
__device__ __forceinline__ uint32_t smem_u32(const void* p) {
    uint32_t a;
    asm("{ .reg .u64 t; cvta.to.shared.u64 t, %1; cvt.u32.u64 %0, t; }" : "=r"(a) : "l"(p));
    return a;
}
__device__ __forceinline__ void ldm_x4(uint32_t* r, uint32_t addr) {
    asm volatile("ldmatrix.sync.aligned.m8n8.x4.shared.b16 {%0,%1,%2,%3}, [%4];"
                 : "=r"(r[0]), "=r"(r[1]), "=r"(r[2]), "=r"(r[3]) : "r"(addr));
}
__device__ __forceinline__ void mma_f16(float* d, const uint32_t* a, const uint32_t* b) {
    asm volatile(
        "mma.sync.aligned.m16n8k16.row.col.f32.f16.f16.f32 "
        "{%0,%1,%2,%3}, {%4,%5,%6,%7}, {%8,%9}, {%0,%1,%2,%3};"
        : "+f"(d[0]), "+f"(d[1]), "+f"(d[2]), "+f"(d[3])
        : "r"(a[0]), "r"(a[1]), "r"(a[2]), "r"(a[3]), "r"(b[0]), "r"(b[1]));
}
__device__ __forceinline__ uint32_t packh2(float a, float b) {
    __half2 p = __floats2half2_rn(a, b);
    return *(uint32_t*)&p;
}
#define CP_ASYNC8(dst, src) \
    asm volatile("cp.async.ca.shared.global [%0], [%1], 8;" :: "r"(dst), "l"(src))
#define CP_COMMIT()  asm volatile("cp.async.commit_group;")
#define CP_WAIT0()   asm volatile("cp.async.wait_group 0;" ::: "memory")

// ---------------------------------------------------------------------------
// K1: conv1 GEMM (fp16 mma.sync) + bias + pair-maxpool + FUSED conv2 score
// reduction + FUSED top-32 selection in the last-finishing CTA.
// Identity used: sum_t2 s[b,t2] = sum_t h[b,t,:].w2[:,(t+1)%3] + T2*b2
// (stride==width==3 => each t is in exactly one conv2 window).
// M-tile 160 x N 128, K chunks of 32, grid 274 = single wave at 2 CTA/SM.
// ---------------------------------------------------------------------------
#define ASTRIDE 40                 // halves per smem row (80B)
#define OFF_A   0
#define OFF_B   12800              // 160 * 80
#define STAGE   23040              // + 128 * 80
#define DYN_SMEM (2 * STAGE)

extern __shared__ char dyn_smem[];

__global__ __launch_bounds__(256, 2) void conv1_mma_kernel(
    const float* __restrict__ x, const float* __restrict__ w1,
    const float* __restrict__ b1, const float* __restrict__ w2,
    const float* __restrict__ b2, const int* __restrict__ seq_lens,
    float* __restrict__ out, long long lens_off, int has_lens)
{
    __shared__ float b1s[NCH];
    __shared__ float w2t[3][H_];
    __shared__ float sbatch[B_];
    __shared__ int   s_last;
    __shared__ float es[B_];
    __shared__ int   rk[B_];

    const int M0  = blockIdx.x * MTILE;
    const int tid = threadIdx.x;
    const int wid = tid >> 5;
    const int lid = tid & 31;
    const int warp_m = (wid >> 2) * 80;
    const int warp_n = (wid & 3) * 32;
    const int g   = lid >> 3;   // ldmatrix lane group
    const int lr  = lid & 7;
    const int t4  = lid & 3;
    const int lg  = lid >> 2;   // mma group row

    // A load geometry: c4 = float col group, rows advance by 32
    const int c4   = (tid & 7) * 4;
    const int row0 = tid >> 3;

    // Precompute per-q row pointers and zero-until-k thresholds
    const float* pq[5];
    int zu[5];
#pragma unroll
    for (int q = 0; q < 5; q++) {
        int row = row0 + 32 * q;
        int r   = M0 + row;
        if (r >= MROWS) {
            zu[q] = KDIM;          // never valid
            pq[q] = x;
        } else {
            int bb = r / T1;
            int tt = r - bb * T1;
            pq[q]  = x + (size_t)bb * T_ * D_ + (size_t)tt * KDIM - D_ + c4;
            zu[q]  = (tt == 0) ? D_ : 0;
        }
    }

    // issue A(0) LDGs now; latency overlaps the transpose+barrier
    float4 rv[5];
#pragma unroll
    for (int q = 0; q < 5; q++) {
        rv[q] = make_float4(0.f, 0.f, 0.f, 0.f);
        if (c4 >= zu[q]) rv[q] = *(const float4*)(pq[q]);
    }

    // ---- phase 0: this CTA's slice of the w1 transpose (fp32 -> fp16) ----
    {
        int base = blockIdx.x * WSLICE;
        int end  = base + WSLICE;
        if (end > WELEMS) end = WELEMS;
        for (int o = base + tid; o < end; o += 256) {
            int c = o / KDIM;
            int k = o - c * KDIM;
            float w = w1[c * KDIM + (k & 511) * 3 + (k >> 9)];
            g_Wh[o] = __float2half_rn(w);
        }
    }
    // ---- single-wave sense-reversing grid barrier ----
    if (tid == 0) {
        unsigned s = *(volatile unsigned*)&g_sense;
        __threadfence();
        unsigned prev = atomicInc(&g_arrive, NTILES - 1);
        if (prev == NTILES - 1) {
            __threadfence();
            *(volatile unsigned*)&g_sense = s ^ 1u;
        } else {
            while (*(volatile unsigned*)&g_sense == s) {}
        }
        __threadfence();
    }
    __syncthreads();

    if (tid < NCH) b1s[tid] = b1[tid];
    if (tid < H_ * 3) {
        int hh = tid / 3, kk = tid - hh * 3;
        w2t[kk][hh] = w2[tid];
    }
    if (tid < B_) sbatch[tid] = 0.f;

    const uint32_t sbase = smem_u32(dyn_smem);

    float acc[5][4][4];
#pragma unroll
    for (int i = 0; i < 5; i++)
#pragma unroll
        for (int j = 0; j < 4; j++)
#pragma unroll
            for (int r = 0; r < 4; r++) acc[i][j][r] = 0.f;

    uint2 ra[5];

    auto load_regs = [&](int k0) {
#pragma unroll
        for (int q = 0; q < 5; q++) {
            float4 v = make_float4(0.f, 0.f, 0.f, 0.f);
            if (k0 + c4 >= zu[q]) v = *(const float4*)(pq[q] + k0);
            ra[q].x = packh2(v.x, v.y);
            ra[q].y = packh2(v.z, v.w);
        }
    };

    auto store_stageA = [&](char* S) {
#pragma unroll
        for (int q = 0; q < 5; q++) {
            int row = row0 + 32 * q;
            int off = row * (ASTRIDE * 2) + c4 * 2;
            *(uint2*)(S + OFF_A + off) = ra[q];
        }
    };

    // B cp.async: 128 rows x 32 halves (64B) per stage, 8B granules
    auto issue_B = [&](uint32_t sdst, int k0) {
#pragma unroll
        for (int q = 0; q < 4; q++) {
            int e    = tid + 256 * q;
            int row  = e >> 3;
            int part = e & 7;
            uint32_t dst = sdst + OFF_B + row * (ASTRIDE * 2) + part * 8;
            const __half* src = g_Wh + (size_t)row * KDIM + k0 + part * 4;
            CP_ASYNC8(dst, src);
        }
    };

    // prologue: stage 0 (A(0) already in rv)
    issue_B(sbase, 0);
    CP_COMMIT();
#pragma unroll
    for (int q = 0; q < 5; q++) {
        ra[q].x = packh2(rv[q].x, rv[q].y);
        ra[q].y = packh2(rv[q].z, rv[q].w);
    }
    store_stageA(dyn_smem);
    CP_WAIT0();
    __syncthreads();

    for (int c = 0; c < NCHUNK; c++) {
        const int buf = c & 1;
        const uint32_t s0 = sbase + buf * STAGE;
        const bool more = (c + 1 < NCHUNK);

        if (more) {
            load_regs((c + 1) * BKC);
            issue_B(sbase + (buf ^ 1) * STAGE, (c + 1) * BKC);
            CP_COMMIT();
        }

#pragma unroll
        for (int kh = 0; kh < 2; kh++) {
            uint32_t bh[4][2];
            const int bkoff = kh * 16 + (g & 1) * 8;
#pragma unroll
            for (int np = 0; np < 2; np++) {
                int brow = warp_n + np * 16 + (g >> 1) * 8 + lr;
                uint32_t bo = (uint32_t)(brow * (ASTRIDE * 2) + bkoff * 2);
                uint32_t t0[4];
                ldm_x4(t0, s0 + OFF_B + bo);
                bh[2 * np][0] = t0[0]; bh[2 * np][1] = t0[1];
                bh[2 * np + 1][0] = t0[2]; bh[2 * np + 1][1] = t0[3];
            }
            const int akoff = kh * 16 + (g >> 1) * 8;
#pragma unroll
            for (int mi = 0; mi < 5; mi++) {
                uint32_t ah[4];
                int arow = warp_m + mi * 16 + (g & 1) * 8 + lr;
                uint32_t ao = (uint32_t)(arow * (ASTRIDE * 2) + akoff * 2);
                ldm_x4(ah, s0 + OFF_A + ao);
#pragma unroll
                for (int ni = 0; ni < 4; ni++)
                    mma_f16(acc[mi][ni], ah, bh[ni]);
            }
        }

        if (more) {
            store_stageA(dyn_smem + (buf ^ 1) * STAGE);
            CP_WAIT0();
            __syncthreads();
        }
    }

    // ---- epilogue: bias + pair-maxpool + conv2-coefficient reduction ----
#pragma unroll
    for (int mi = 0; mi < 5; mi++) {
        int r0 = M0 + warp_m + mi * 16 + lg;
        int r1 = r0 + 8;
        float sum0 = 0.f, sum1 = 0.f;
        int b0 = 0, ph0 = 0, b1i = 0, ph1 = 0;
        bool v0 = (r0 < MROWS), v1 = (r1 < MROWS);
        if (v0) { b0 = r0 / T1; int tt = r0 - b0 * T1; ph0 = (tt + 1) % 3; }
        if (v1) { b1i = r1 / T1; int tt = r1 - b1i * T1; ph1 = (tt + 1) % 3; }
#pragma unroll
        for (int ni = 0; ni < 4; ni++) {
            int col = warp_n + ni * 8 + t4 * 2;
            int h   = col >> 1;
            float bb0 = b1s[col], bb1 = b1s[col + 1];
            if (v0) sum0 += fmaxf(acc[mi][ni][0] + bb0, acc[mi][ni][1] + bb1) * w2t[ph0][h];
            if (v1) sum1 += fmaxf(acc[mi][ni][2] + bb0, acc[mi][ni][3] + bb1) * w2t[ph1][h];
        }
        if (v0) atomicAdd(&sbatch[b0], sum0);
        if (v1) atomicAdd(&sbatch[b1i], sum1);
    }
    __syncthreads();
    if (tid < B_) atomicAdd(&g_part[tid], sbatch[tid]);
    __threadfence();
    __syncthreads();
    if (tid == 0) {
        unsigned prev = atomicInc(&g_done, NTILES - 1);   // wraps -> self-reset
        s_last = (prev == NTILES - 1) ? 1 : 0;
    }
    __syncthreads();
    if (!s_last) return;

    // ---- last CTA: est + top-32 selection (jax tie-break: lower idx wins) ----
    if (tid < B_) {
        float tot = *(volatile float*)&g_part[tid];
        tot += (float)T2 * b2[0];
        int L   = seq_lens[tid];
        int sl1 = (L + 2) / 3;
        int sl2 = (sl1 + 2) / 3;
        es[tid] = tot / (float)sl2;
        g_part[tid] = 0.f;          // reset for next graph replay
    }
    __syncthreads();
    if (tid < B_) {
        float ei = es[tid];
        int r = 0;
#pragma unroll
        for (int j = 0; j < B_; j++) {
            float ej = es[j];
            if (ej > ei || (ej == ei && j < tid)) r++;
        }
        rk[tid] = r;
    }
    __syncthreads();
    if (tid < B_ && rk[tid] < KSEL) {
        int slot = 0;
        for (int j = 0; j < tid; j++)
            if (rk[j] < KSEL) slot++;
        g_idx[slot] = tid;
        if (has_lens) out[lens_off + slot] = (float)seq_lens[tid];
    }
}

// ---------------------------------------------------------------------------
// K2: gather x_sel = x[idx][:, :max_time, :], 2 float4 per thread
// ---------------------------------------------------------------------------
__global__ void gather_kernel(const float* __restrict__ x,
                              float* __restrict__ out, int max_time)
{
    const int s = blockIdx.y;
    long long n4 = (long long)max_time * (D_ / 4);
    long long i0 = (long long)blockIdx.x * 512 + threadIdx.x;
    int src_b = g_idx[s];
    const float4* src = (const float4*)(x + (size_t)src_b * T_ * D_);
    float4*       dst = (float4*)(out + (size_t)s * max_time * D_);
    if (i0 < n4) dst[i0] = src[i0];
    long long i1 = i0 + 256;
    if (i1 < n4) dst[i1] = src[i1];
}

// ---------------------------------------------------------------------------
// Host launcher
// ---------------------------------------------------------------------------
extern "C" void kernel_launch(void* const* d_in, const int* in_sizes, int n_in,
                              void* d_out, int out_size)
{
    const float* x        = (const float*)d_in[0];
    const int*   seq_lens = (const int*)  d_in[1];
    const float* w1       = (const float*)d_in[2];
    const float* b1       = (const float*)d_in[3];
    const float* w2       = (const float*)d_in[4];
    const float* b2       = (const float*)d_in[5];
    float* out = (float*)d_out;

    const long long row_elems = (long long)KSEL * D_;
    int has_lens = ((long long)out_size % row_elems) != 0;
    long long mt = has_lens ? ((long long)out_size - KSEL) / row_elems
                            : (long long)out_size / row_elems;
    int max_time = (int)mt;

    cudaFuncSetAttribute(conv1_mma_kernel,
                         cudaFuncAttributeMaxDynamicSharedMemorySize, DYN_SMEM);

    conv1_mma_kernel<<<NTILES, 256, DYN_SMEM>>>(
        x, w1, b1, w2, b2, seq_lens, out,
        (long long)KSEL * max_time * D_, has_lens);

    long long n4 = (long long)max_time * (D_ / 4);
    dim3 g4((unsigned)((n4 + 511) / 512), KSEL);
    gather_kernel<<<g4, 256>>>(x, out, max_time);
}

// round 14
// speedup vs baseline: 1.4531x; 1.4531x over previous
#include <cuda_runtime.h>
#include <cuda_fp16.h>
#include <cstdint>

// Problem constants
#define B_   64
#define T_   2048
#define D_   512
#define H_   64
#define T1   683      // conv1 output length
#define T2   228      // conv2 output length
#define KDIM 1536     // 3*512
#define NCH  128      // 2*H
#define KSEL 32       // top-k

#define NCHUNK 48     // KDIM / 32
#define BKC    32     // K elems per chunk

#define MROWS (B_ * T1)   // 43712 flattened (b,t) rows
#define MTILE 160
#define NTILES ((MROWS + MTILE - 1) / MTILE)   // 274
#define WELEMS (NCH * KDIM)                     // 196608
#define WSLICE ((WELEMS + NTILES - 1) / NTILES) // 718

// Device scratch
__device__ __half g_Wh[NCH * KDIM];   // weights [c][k] fp16
__device__ float g_part[B_];          // per-batch score partials (zero-init; sel kernel resets)
__device__ int   g_idx[KSEL];
__device__ unsigned g_arrive = 0;     // start grid barrier counter (wraps -> self-reset)
__device__ unsigned g_sense = 0;      // start grid barrier sense (alternates per replay)

// ---------------------------------------------------------------------------
// helpers
// ---------------------------------------------------------------------------
__device__ __forceinline__ uint32_t smem_u32(const void* p) {
    uint32_t a;
    asm("{ .reg .u64 t; cvta.to.shared.u64 t, %1; cvt.u32.u64 %0, t; }" : "=r"(a) : "l"(p));
    return a;
}
__device__ __forceinline__ void ldm_x4(uint32_t* r, uint32_t addr) {
    asm volatile("ldmatrix.sync.aligned.m8n8.x4.shared.b16 {%0,%1,%2,%3}, [%4];"
                 : "=r"(r[0]), "=r"(r[1]), "=r"(r[2]), "=r"(r[3]) : "r"(addr));
}
__device__ __forceinline__ void mma_f16(float* d, const uint32_t* a, const uint32_t* b) {
    asm volatile(
        "mma.sync.aligned.m16n8k16.row.col.f32.f16.f16.f32 "
        "{%0,%1,%2,%3}, {%4,%5,%6,%7}, {%8,%9}, {%0,%1,%2,%3};"
        : "+f"(d[0]), "+f"(d[1]), "+f"(d[2]), "+f"(d[3])
        : "r"(a[0]), "r"(a[1]), "r"(a[2]), "r"(a[3]), "r"(b[0]), "r"(b[1]));
}
__device__ __forceinline__ uint32_t packh2(float a, float b) {
    __half2 p = __floats2half2_rn(a, b);
    return *(uint32_t*)&p;
}
#define CP_ASYNC8(dst, src) \
    asm volatile("cp.async.ca.shared.global [%0], [%1], 8;" :: "r"(dst), "l"(src))
#define CP_COMMIT()  asm volatile("cp.async.commit_group;")
#define CP_WAIT0()   asm volatile("cp.async.wait_group 0;" ::: "memory")

// ---------------------------------------------------------------------------
// K1: conv1 GEMM (fp16 mma.sync) + bias + pair-maxpool + conv2 fold-in.
// Identity: sum_t2 s[b,t2] = sum_t h[b,t,:].w2[:,(t+1)%3] + T2*b2
// (stride==width==3 => each t is in exactly one conv2 window).
// Epilogue: t4-shuffle reduce -> few smem atomics -> 64 global atomics.
// NO selection state in this kernel (keeps loop registers at 128).
// M-tile 160 x N 128, K chunks of 32, grid 274 = single wave at 2 CTA/SM.
// ---------------------------------------------------------------------------
#define ASTRIDE 40                 // halves per smem row (80B)
#define OFF_A   0
#define OFF_B   12800              // 160 * 80
#define STAGE   23040              // + 128 * 80
#define DYN_SMEM (2 * STAGE)

extern __shared__ char dyn_smem[];

__global__ __launch_bounds__(256, 2) void conv1_mma_kernel(
    const float* __restrict__ x, const float* __restrict__ w1,
    const float* __restrict__ b1, const float* __restrict__ w2)
{
    __shared__ float b1s[NCH];
    __shared__ float w2t[3][H_];
    __shared__ float sbatch[B_];

    const int M0  = blockIdx.x * MTILE;
    const int tid = threadIdx.x;
    const int wid = tid >> 5;
    const int lid = tid & 31;
    const int warp_m = (wid >> 2) * 80;
    const int warp_n = (wid & 3) * 32;
    const int g   = lid >> 3;   // ldmatrix lane group
    const int lr  = lid & 7;
    const int t4  = lid & 3;
    const int lg  = lid >> 2;   // mma group row

    // A load geometry: c4 = float col group, rows advance by 32
    const int c4   = (tid & 7) * 4;
    const int row0 = tid >> 3;

    // Precompute per-q row pointers and zero-until-k thresholds
    const float* pq[5];
    int zu[5];
#pragma unroll
    for (int q = 0; q < 5; q++) {
        int row = row0 + 32 * q;
        int r   = M0 + row;
        if (r >= MROWS) {
            zu[q] = KDIM;          // never valid
            pq[q] = x;
        } else {
            int bb = r / T1;
            int tt = r - bb * T1;
            pq[q]  = x + (size_t)bb * T_ * D_ + (size_t)tt * KDIM - D_ + c4;
            zu[q]  = (tt == 0) ? D_ : 0;
        }
    }

    // issue A(0) LDGs now; latency overlaps the transpose+barrier
    float4 rv[5];
#pragma unroll
    for (int q = 0; q < 5; q++) {
        rv[q] = make_float4(0.f, 0.f, 0.f, 0.f);
        if (c4 >= zu[q]) rv[q] = *(const float4*)(pq[q]);
    }

    // ---- phase 0: this CTA's slice of the w1 transpose (fp32 -> fp16) ----
    {
        int base = blockIdx.x * WSLICE;
        int end  = base + WSLICE;
        if (end > WELEMS) end = WELEMS;
        for (int o = base + tid; o < end; o += 256) {
            int c = o / KDIM;
            int k = o - c * KDIM;
            float w = w1[c * KDIM + (k & 511) * 3 + (k >> 9)];
            g_Wh[o] = __float2half_rn(w);
        }
    }
    // ---- single-wave sense-reversing grid barrier ----
    if (tid == 0) {
        unsigned s = *(volatile unsigned*)&g_sense;
        __threadfence();
        unsigned prev = atomicInc(&g_arrive, NTILES - 1);
        if (prev == NTILES - 1) {
            __threadfence();
            *(volatile unsigned*)&g_sense = s ^ 1u;
        } else {
            while (*(volatile unsigned*)&g_sense == s) {}
        }
        __threadfence();
    }
    __syncthreads();

    if (tid < NCH) b1s[tid] = b1[tid];
    if (tid < H_ * 3) {
        int hh = tid / 3, kk = tid - hh * 3;
        w2t[kk][hh] = w2[tid];     // w2 dead after this -> no loop register
    }
    if (tid < B_) sbatch[tid] = 0.f;

    const uint32_t sbase = smem_u32(dyn_smem);

    float acc[5][4][4];
#pragma unroll
    for (int i = 0; i < 5; i++)
#pragma unroll
        for (int j = 0; j < 4; j++)
#pragma unroll
            for (int r = 0; r < 4; r++) acc[i][j][r] = 0.f;

    uint2 ra[5];

    auto load_regs = [&](int k0) {
#pragma unroll
        for (int q = 0; q < 5; q++) {
            float4 v = make_float4(0.f, 0.f, 0.f, 0.f);
            if (k0 + c4 >= zu[q]) v = *(const float4*)(pq[q] + k0);
            ra[q].x = packh2(v.x, v.y);
            ra[q].y = packh2(v.z, v.w);
        }
    };

    auto store_stageA = [&](char* S) {
#pragma unroll
        for (int q = 0; q < 5; q++) {
            int row = row0 + 32 * q;
            int off = row * (ASTRIDE * 2) + c4 * 2;
            *(uint2*)(S + OFF_A + off) = ra[q];
        }
    };

    // B cp.async: 128 rows x 32 halves (64B) per stage, 8B granules
    auto issue_B = [&](uint32_t sdst, int k0) {
#pragma unroll
        for (int q = 0; q < 4; q++) {
            int e    = tid + 256 * q;
            int row  = e >> 3;
            int part = e & 7;
            uint32_t dst = sdst + OFF_B + row * (ASTRIDE * 2) + part * 8;
            const __half* src = g_Wh + (size_t)row * KDIM + k0 + part * 4;
            CP_ASYNC8(dst, src);
        }
    };

    // prologue: stage 0 (A(0) already in rv)
    issue_B(sbase, 0);
    CP_COMMIT();
#pragma unroll
    for (int q = 0; q < 5; q++) {
        ra[q].x = packh2(rv[q].x, rv[q].y);
        ra[q].y = packh2(rv[q].z, rv[q].w);
    }
    store_stageA(dyn_smem);
    CP_WAIT0();
    __syncthreads();

    for (int c = 0; c < NCHUNK; c++) {
        const int buf = c & 1;
        const uint32_t s0 = sbase + buf * STAGE;
        const bool more = (c + 1 < NCHUNK);

        if (more) {
            load_regs((c + 1) * BKC);
            issue_B(sbase + (buf ^ 1) * STAGE, (c + 1) * BKC);
            CP_COMMIT();
        }

#pragma unroll
        for (int kh = 0; kh < 2; kh++) {
            uint32_t bh[4][2];
            const int bkoff = kh * 16 + (g & 1) * 8;
#pragma unroll
            for (int np = 0; np < 2; np++) {
                int brow = warp_n + np * 16 + (g >> 1) * 8 + lr;
                uint32_t bo = (uint32_t)(brow * (ASTRIDE * 2) + bkoff * 2);
                uint32_t t0[4];
                ldm_x4(t0, s0 + OFF_B + bo);
                bh[2 * np][0] = t0[0]; bh[2 * np][1] = t0[1];
                bh[2 * np + 1][0] = t0[2]; bh[2 * np + 1][1] = t0[3];
            }
            const int akoff = kh * 16 + (g >> 1) * 8;
#pragma unroll
            for (int mi = 0; mi < 5; mi++) {
                uint32_t ah[4];
                int arow = warp_m + mi * 16 + (g & 1) * 8 + lr;
                uint32_t ao = (uint32_t)(arow * (ASTRIDE * 2) + akoff * 2);
                ldm_x4(ah, s0 + OFF_A + ao);
#pragma unroll
                for (int ni = 0; ni < 4; ni++)
                    mma_f16(acc[mi][ni], ah, bh[ni]);
            }
        }

        if (more) {
            store_stageA(dyn_smem + (buf ^ 1) * STAGE);
            CP_WAIT0();
            __syncthreads();
        }
    }

    // ---- epilogue: bias + pair-maxpool + conv2-coefficient reduction ----
#pragma unroll
    for (int mi = 0; mi < 5; mi++) {
        int r0 = M0 + warp_m + mi * 16 + lg;
        int r1 = r0 + 8;
        float sum0 = 0.f, sum1 = 0.f;
        bool v0 = (r0 < MROWS), v1 = (r1 < MROWS);
        int b0 = 0, ph0 = 0, b1i = 0, ph1 = 0;
        if (v0) { b0 = r0 / T1; int tt = r0 - b0 * T1; ph0 = (tt + 1) % 3; }
        if (v1) { b1i = r1 / T1; int tt = r1 - b1i * T1; ph1 = (tt + 1) % 3; }
#pragma unroll
        for (int ni = 0; ni < 4; ni++) {
            int col = warp_n + ni * 8 + t4 * 2;
            int h   = col >> 1;
            float bb0 = b1s[col], bb1 = b1s[col + 1];
            if (v0) sum0 += fmaxf(acc[mi][ni][0] + bb0, acc[mi][ni][1] + bb1) * w2t[ph0][h];
            if (v1) sum1 += fmaxf(acc[mi][ni][2] + bb0, acc[mi][ni][3] + bb1) * w2t[ph1][h];
        }
        // reduce across t4 lanes (same row) before touching smem
        sum0 += __shfl_xor_sync(0xFFFFFFFFu, sum0, 1);
        sum0 += __shfl_xor_sync(0xFFFFFFFFu, sum0, 2);
        sum1 += __shfl_xor_sync(0xFFFFFFFFu, sum1, 1);
        sum1 += __shfl_xor_sync(0xFFFFFFFFu, sum1, 2);
        if (t4 == 0) {
            if (v0) atomicAdd(&sbatch[b0], sum0);
            if (v1) atomicAdd(&sbatch[b1i], sum1);
        }
    }
    __syncthreads();
    if (tid < B_) atomicAdd(&g_part[tid], sbatch[tid]);
}

// ---------------------------------------------------------------------------
// K2: est + top-32 selection (1 block, 64 threads). Reads g_part, resets it.
// jax tie-break: lower index wins; g_idx ascending.
// ---------------------------------------------------------------------------
__global__ void sel_kernel(const int* __restrict__ seq_lens,
                           const float* __restrict__ b2,
                           float* __restrict__ out,
                           long long lens_off, int has_lens)
{
    __shared__ float es[B_];
    __shared__ int   rk[B_];
    int i = threadIdx.x;
    float tot = g_part[i] + (float)T2 * b2[0];
    int L   = seq_lens[i];
    int sl1 = (L + 2) / 3;
    int sl2 = (sl1 + 2) / 3;
    es[i] = tot / (float)sl2;
    g_part[i] = 0.f;              // reset for next graph replay
    __syncthreads();
    float ei = es[i];
    int r = 0;
#pragma unroll
    for (int j = 0; j < B_; j++) {
        float ej = es[j];
        if (ej > ei || (ej == ei && j < i)) r++;
    }
    rk[i] = r;
    __syncthreads();
    if (rk[i] < KSEL) {
        int slot = 0;
        for (int j = 0; j < i; j++)
            if (rk[j] < KSEL) slot++;
        g_idx[slot] = i;
        if (has_lens) out[lens_off + slot] = (float)seq_lens[i];
    }
}

// ---------------------------------------------------------------------------
// K3: gather x_sel = x[idx][:, :max_time, :], 2 float4 per thread
// ---------------------------------------------------------------------------
__global__ void gather_kernel(const float* __restrict__ x,
                              float* __restrict__ out, int max_time)
{
    const int s = blockIdx.y;
    long long n4 = (long long)max_time * (D_ / 4);
    long long i0 = (long long)blockIdx.x * 512 + threadIdx.x;
    int src_b = g_idx[s];
    const float4* src = (const float4*)(x + (size_t)src_b * T_ * D_);
    float4*       dst = (float4*)(out + (size_t)s * max_time * D_);
    if (i0 < n4) dst[i0] = src[i0];
    long long i1 = i0 + 256;
    if (i1 < n4) dst[i1] = src[i1];
}

// ---------------------------------------------------------------------------
// Host launcher
// ---------------------------------------------------------------------------
extern "C" void kernel_launch(void* const* d_in, const int* in_sizes, int n_in,
                              void* d_out, int out_size)
{
    const float* x        = (const float*)d_in[0];
    const int*   seq_lens = (const int*)  d_in[1];
    const float* w1       = (const float*)d_in[2];
    const float* b1       = (const float*)d_in[3];
    const float* w2       = (const float*)d_in[4];
    const float* b2       = (const float*)d_in[5];
    float* out = (float*)d_out;

    const long long row_elems = (long long)KSEL * D_;
    int has_lens = ((long long)out_size % row_elems) != 0;
    long long mt = has_lens ? ((long long)out_size - KSEL) / row_elems
                            : (long long)out_size / row_elems;
    int max_time = (int)mt;

    cudaFuncSetAttribute(conv1_mma_kernel,
                         cudaFuncAttributeMaxDynamicSharedMemorySize, DYN_SMEM);

    conv1_mma_kernel<<<NTILES, 256, DYN_SMEM>>>(x, w1, b1, w2);

    sel_kernel<<<1, B_>>>(seq_lens, b2, out,
                          (long long)KSEL * max_time * D_, has_lens);

    long long n4 = (long long)max_time * (D_ / 4);
    dim3 g4((unsigned)((n4 + 511) / 512), KSEL);
    gather_kernel<<<g4, 256>>>(x, out, max_time);
}

// round 15
// speedup vs baseline: 1.5282x; 1.0517x over previous
#include <cuda_runtime.h>
#include <cuda_fp16.h>
#include <cstdint>

// Problem constants
#define B_   64
#define T_   2048
#define D_   512
#define H_   64
#define T1   683      // conv1 output length
#define T2   228      // conv2 output length
#define KDIM 1536     // 3*512
#define NCH  128      // 2*H
#define KSEL 32       // top-k

#define NCHUNK 48     // KDIM / 32
#define BKC    32     // K elems per chunk

#define MROWS (B_ * T1)   // 43712 flattened (b,t) rows
#define MTILE 160
#define NTILES ((MROWS + MTILE - 1) / MTILE)   // 274
#define WELEMS (NCH * KDIM)                     // 196608
#define WSLICE ((WELEMS + NTILES - 1) / NTILES) // 718

// Device scratch
__device__ __half g_Wh[NCH * KDIM];   // weights [c][k] fp16
__device__ float g_h[(size_t)MROWS * H_];   // [r = b*683+t][h]
__device__ float g_est[B_];
__device__ int   g_idx[KSEL];
__device__ unsigned g_cnt = 0;        // conv2_sel last-block counter (wraps -> self-reset)
__device__ unsigned g_arrive = 0;     // conv1 grid barrier counter (wraps -> self-reset)
__device__ unsigned g_sense = 0;      // conv1 grid barrier sense (alternates per replay)

// ---------------------------------------------------------------------------
// helpers
// ---------------------------------------------------------------------------
__device__ __forceinline__ uint32_t smem_u32(const void* p) {
    uint32_t a;
    asm("{ .reg .u64 t; cvta.to.shared.u64 t, %1; cvt.u32.u64 %0, t; }" : "=r"(a) : "l"(p));
    return a;
}
__device__ __forceinline__ void ldm_x4(uint32_t* r, uint32_t addr) {
    asm volatile("ldmatrix.sync.aligned.m8n8.x4.shared.b16 {%0,%1,%2,%3}, [%4];"
                 : "=r"(r[0]), "=r"(r[1]), "=r"(r[2]), "=r"(r[3]) : "r"(addr));
}
__device__ __forceinline__ void mma_f16(float* d, const uint32_t* a, const uint32_t* b) {
    asm volatile(
        "mma.sync.aligned.m16n8k16.row.col.f32.f16.f16.f32 "
        "{%0,%1,%2,%3}, {%4,%5,%6,%7}, {%8,%9}, {%0,%1,%2,%3};"
        : "+f"(d[0]), "+f"(d[1]), "+f"(d[2]), "+f"(d[3])
        : "r"(a[0]), "r"(a[1]), "r"(a[2]), "r"(a[3]), "r"(b[0]), "r"(b[1]));
}
__device__ __forceinline__ uint32_t packh2(float a, float b) {
    __half2 p = __floats2half2_rn(a, b);
    return *(uint32_t*)&p;
}
#define CP_ASYNC8(dst, src) \
    asm volatile("cp.async.ca.shared.global [%0], [%1], 8;" :: "r"(dst), "l"(src))
#define CP_COMMIT()  asm volatile("cp.async.commit_group;")
#define CP_WAIT0()   asm volatile("cp.async.wait_group 0;" ::: "memory")

// ---------------------------------------------------------------------------
// K1: conv1 = fused w1 transpose (grid-barrier) + fp16 mma.sync GEMM + bias
// + pair-maxpool. M-tile 160 x N 128, K chunks of 32. Grid = 274 (single
// wave at 2 CTA/SM). R9-exact structure (the 142.0us champion).
// ---------------------------------------------------------------------------
#define ASTRIDE 40                 // halves per smem row (80B)
#define OFF_A   0
#define OFF_B   12800              // 160 * 80
#define STAGE   23040              // + 128 * 80
#define DYN_SMEM (2 * STAGE)

extern __shared__ char dyn_smem[];

__global__ __launch_bounds__(256, 2) void conv1_mma_kernel(
    const float* __restrict__ x, const float* __restrict__ w1,
    const float* __restrict__ b1)
{
    __shared__ float b1s[NCH];

    const int M0  = blockIdx.x * MTILE;
    const int tid = threadIdx.x;
    const int wid = tid >> 5;
    const int lid = tid & 31;
    const int warp_m = (wid >> 2) * 80;
    const int warp_n = (wid & 3) * 32;
    const int g   = lid >> 3;   // ldmatrix lane group
    const int lr  = lid & 7;
    const int t4  = lid & 3;
    const int lg  = lid >> 2;   // mma group row

    // ---- phase 0: this CTA's slice of the w1 transpose (fp32 -> fp16) ----
    {
        int base = blockIdx.x * WSLICE;
        int end  = base + WSLICE;
        if (end > WELEMS) end = WELEMS;
        for (int o = base + tid; o < end; o += 256) {
            int c = o / KDIM;
            int k = o - c * KDIM;
            float w = w1[c * KDIM + (k & 511) * 3 + (k >> 9)];
            g_Wh[o] = __float2half_rn(w);
        }
    }
    // ---- single-wave sense-reversing grid barrier ----
    if (tid == 0) {
        unsigned s = *(volatile unsigned*)&g_sense;
        __threadfence();
        unsigned prev = atomicInc(&g_arrive, NTILES - 1);
        if (prev == NTILES - 1) {
            __threadfence();
            *(volatile unsigned*)&g_sense = s ^ 1u;
        } else {
            while (*(volatile unsigned*)&g_sense == s) {}
        }
        __threadfence();
    }
    __syncthreads();

    if (tid < NCH) b1s[tid] = b1[tid];

    const uint32_t sbase = smem_u32(dyn_smem);

    float acc[5][4][4];
#pragma unroll
    for (int i = 0; i < 5; i++)
#pragma unroll
        for (int j = 0; j < 4; j++)
#pragma unroll
            for (int r = 0; r < 4; r++) acc[i][j][r] = 0.f;

    // A load geometry: c4 = float col group, rows advance by 32
    const int c4   = (tid & 7) * 4;
    const int row0 = tid >> 3;

    // Precompute per-q row pointers and zero-until-k thresholds
    const float* pq[5];
    int zu[5];
#pragma unroll
    for (int q = 0; q < 5; q++) {
        int row = row0 + 32 * q;
        int r   = M0 + row;
        if (r >= MROWS) {
            zu[q] = KDIM;          // never valid
            pq[q] = x;
        } else {
            int bb = r / T1;
            int tt = r - bb * T1;
            pq[q]  = x + (size_t)bb * T_ * D_ + (size_t)tt * KDIM - D_ + c4;
            zu[q]  = (tt == 0) ? D_ : 0;
        }
    }

    uint2 ra[5];

    auto load_regs = [&](int k0) {
#pragma unroll
        for (int q = 0; q < 5; q++) {
            float4 v = make_float4(0.f, 0.f, 0.f, 0.f);
            if (k0 + c4 >= zu[q]) v = *(const float4*)(pq[q] + k0);
            ra[q].x = packh2(v.x, v.y);
            ra[q].y = packh2(v.z, v.w);
        }
    };

    auto store_stageA = [&](char* S) {
#pragma unroll
        for (int q = 0; q < 5; q++) {
            int row = row0 + 32 * q;
            int off = row * (ASTRIDE * 2) + c4 * 2;
            *(uint2*)(S + OFF_A + off) = ra[q];
        }
    };

    // B cp.async: 128 rows x 32 halves (64B) per stage, 8B granules
    auto issue_B = [&](uint32_t sdst, int k0) {
#pragma unroll
        for (int q = 0; q < 4; q++) {
            int e    = tid + 256 * q;
            int row  = e >> 3;
            int part = e & 7;
            uint32_t dst = sdst + OFF_B + row * (ASTRIDE * 2) + part * 8;
            const __half* src = g_Wh + (size_t)row * KDIM + k0 + part * 4;
            CP_ASYNC8(dst, src);
        }
    };

    // prologue: stage 0
    load_regs(0);
    issue_B(sbase, 0);
    CP_COMMIT();
    store_stageA(dyn_smem);
    CP_WAIT0();
    __syncthreads();

    for (int c = 0; c < NCHUNK; c++) {
        const int buf = c & 1;
        const uint32_t s0 = sbase + buf * STAGE;

        if (c + 1 < NCHUNK) {
            load_regs((c + 1) * BKC);
            issue_B(sbase + (buf ^ 1) * STAGE, (c + 1) * BKC);
            CP_COMMIT();
        }

#pragma unroll
        for (int kh = 0; kh < 2; kh++) {
            uint32_t bh[4][2];
            const int bkoff = kh * 16 + (g & 1) * 8;
#pragma unroll
            for (int np = 0; np < 2; np++) {
                int brow = warp_n + np * 16 + (g >> 1) * 8 + lr;
                uint32_t bo = (uint32_t)(brow * (ASTRIDE * 2) + bkoff * 2);
                uint32_t t0[4];
                ldm_x4(t0, s0 + OFF_B + bo);
                bh[2 * np][0] = t0[0]; bh[2 * np][1] = t0[1];
                bh[2 * np + 1][0] = t0[2]; bh[2 * np + 1][1] = t0[3];
            }
            const int akoff = kh * 16 + (g >> 1) * 8;
#pragma unroll
            for (int mi = 0; mi < 5; mi++) {
                uint32_t ah[4];
                int arow = warp_m + mi * 16 + (g & 1) * 8 + lr;
                uint32_t ao = (uint32_t)(arow * (ASTRIDE * 2) + akoff * 2);
                ldm_x4(ah, s0 + OFF_A + ao);
#pragma unroll
                for (int ni = 0; ni < 4; ni++)
                    mma_f16(acc[mi][ni], ah, bh[ni]);
            }
        }

        if (c + 1 < NCHUNK) store_stageA(dyn_smem + (buf ^ 1) * STAGE);
        CP_WAIT0();
        __syncthreads();
    }

    // epilogue: bias + pair-maxpool, write g_h[r][h]
#pragma unroll
    for (int mi = 0; mi < 5; mi++) {
        int r0 = M0 + warp_m + mi * 16 + lg;
        int r1 = r0 + 8;
#pragma unroll
        for (int ni = 0; ni < 4; ni++) {
            int col = warp_n + ni * 8 + t4 * 2;
            int h   = col >> 1;
            float bb0 = b1s[col], bb1 = b1s[col + 1];
            if (r0 < MROWS)
                g_h[(size_t)r0 * H_ + h] =
                    fmaxf(acc[mi][ni][0] + bb0, acc[mi][ni][1] + bb1);
            if (r1 < MROWS)
                g_h[(size_t)r1 * H_ + h] =
                    fmaxf(acc[mi][ni][2] + bb0, acc[mi][ni][3] + bb1);
        }
    }
}

// ---------------------------------------------------------------------------
// K2: conv2 + score + FUSED top-32 selection (last block does select).
// ---------------------------------------------------------------------------
__global__ __launch_bounds__(256) void conv2_sel_kernel(
    const float* __restrict__ w2, const float* __restrict__ b2,
    const int* __restrict__ seq_lens, float* __restrict__ out,
    long long lens_off, int has_lens)
{
    const int b   = blockIdx.x;
    const int tid = threadIdx.x;
    const int wid = tid >> 5;
    const int lid = tid & 31;
    __shared__ float w2t[3][H_];
    __shared__ float part[8];
    __shared__ int   s_last;
    __shared__ float es[B_];
    __shared__ int   rk[B_];

    if (tid < H_ * 3) {
        int hh = tid / 3, kk = tid - hh * 3;
        w2t[kk][hh] = w2[tid];
    }
    __syncthreads();

    float wk0[3], wk1[3];
#pragma unroll
    for (int kk = 0; kk < 3; kk++) {
        wk0[kk] = w2t[kk][2 * lid];
        wk1[kk] = w2t[kk][2 * lid + 1];
    }

    const float* hb = g_h + (size_t)b * T1 * H_;
    float s = 0.f;
    for (int t2 = wid; t2 < T2; t2 += 8) {
        int base = t2 * 3 - 1;
#pragma unroll
        for (int kk = 0; kk < 3; kk++) {
            int tp = base + kk;
            if (tp >= 0) {
                float2 v = *(const float2*)(hb + (size_t)tp * H_ + 2 * lid);
                s += v.x * wk0[kk] + v.y * wk1[kk];
            }
        }
    }
#pragma unroll
    for (int o = 16; o > 0; o >>= 1)
        s += __shfl_xor_sync(0xFFFFFFFFu, s, o);
    if (lid == 0) part[wid] = s;
    __syncthreads();
    if (tid == 0) {
        float tot = 0.f;
#pragma unroll
        for (int w = 0; w < 8; w++) tot += part[w];
        tot += (float)T2 * b2[0];
        int L   = seq_lens[b];
        int sl1 = (L + 2) / 3;
        int sl2 = (sl1 + 2) / 3;
        g_est[b] = tot / (float)sl2;
        __threadfence();
        // wraps to 0 after B_ increments -> self-resetting across graph replays
        unsigned prev = atomicInc(&g_cnt, B_ - 1);
        s_last = (prev == B_ - 1) ? 1 : 0;
    }
    __syncthreads();
    if (!s_last) return;

    // ---- selection (threads 0..63), jax tie-break: lower index wins ----
    if (tid < B_) es[tid] = g_est[tid];
    __syncthreads();
    if (tid < B_) {
        float ei = es[tid];
        int r = 0;
#pragma unroll
        for (int j = 0; j < B_; j++) {
            float ej = es[j];
            if (ej > ei || (ej == ei && j < tid)) r++;
        }
        rk[tid] = r;
    }
    __syncthreads();
    if (tid < B_ && rk[tid] < KSEL) {
        int slot = 0;
        for (int j = 0; j < tid; j++)
            if (rk[j] < KSEL) slot++;
        g_idx[slot] = tid;
        if (has_lens) out[lens_off + slot] = (float)seq_lens[tid];
    }
}

// ---------------------------------------------------------------------------
// K3: gather x_sel = x[idx][:, :max_time, :], 4 float4 per thread
// ---------------------------------------------------------------------------
__global__ void gather_kernel(const float* __restrict__ x,
                              float* __restrict__ out, int max_time)
{
    const int s = blockIdx.y;
    long long n4 = (long long)max_time * (D_ / 4);
    long long i0 = (long long)blockIdx.x * 1024 + threadIdx.x;
    int src_b = g_idx[s];
    const float4* src = (const float4*)(x + (size_t)src_b * T_ * D_);
    float4*       dst = (float4*)(out + (size_t)s * max_time * D_);
#pragma unroll
    for (int q = 0; q < 4; q++) {
        long long i = i0 + q * 256;
        if (i < n4) dst[i] = src[i];
    }
}

// ---------------------------------------------------------------------------
// Host launcher
// ---------------------------------------------------------------------------
extern "C" void kernel_launch(void* const* d_in, const int* in_sizes, int n_in,
                              void* d_out, int out_size)
{
    const float* x        = (const float*)d_in[0];
    const int*   seq_lens = (const int*)  d_in[1];
    const float* w1       = (const float*)d_in[2];
    const float* b1       = (const float*)d_in[3];
    const float* w2       = (const float*)d_in[4];
    const float* b2       = (const float*)d_in[5];
    float* out = (float*)d_out;

    const long long row_elems = (long long)KSEL * D_;
    int has_lens = ((long long)out_size % row_elems) != 0;
    long long mt = has_lens ? ((long long)out_size - KSEL) / row_elems
                            : (long long)out_size / row_elems;
    int max_time = (int)mt;

    cudaFuncSetAttribute(conv1_mma_kernel,
                         cudaFuncAttributeMaxDynamicSharedMemorySize, DYN_SMEM);

    conv1_mma_kernel<<<NTILES, 256, DYN_SMEM>>>(x, w1, b1);

    conv2_sel_kernel<<<B_, 256>>>(w2, b2, seq_lens, out,
                                  (long long)KSEL * max_time * D_, has_lens);

    long long n4 = (long long)max_time * (D_ / 4);
    dim3 g4((unsigned)((n4 + 1023) / 1024), KSEL);
    gather_kernel<<<g4, 256>>>(x, out, max_time);
}